// round 4
// baseline (speedup 1.0000x reference)
#include <cuda_runtime.h>
#include <math.h>

#ifndef M_PI
#define M_PI 3.14159265358979323846
#endif

#define MM 4096
#define NN 4096
#define RNK 10
#define TRI 55        // 10*11/2 packed lower triangle
#define NWRD 128      // 4096/32 mask words per row
#define GSEG 8        // row segments for gram kernel
#define CH 256        // row chunk staged in smem
#define N_LAYERS 3
#define HUB_ITERS 2

// ---------------- device scratch (static: no allocation APIs) ----------------
__device__ float    g_U[MM*RNK];
__device__ float    g_V[RNK*NN];
__device__ float    g_XT[(size_t)MM*NN];      // 64 MB
__device__ unsigned g_mb [MM*NWRD];           // mask bits of X  (row-major)
__device__ unsigned g_mbT[NN*NWRD];           // mask bits of X^T
__device__ float    g_nobs_col[NN];
__device__ float    g_nobs_row[MM];
__device__ float    g_Gpart[GSEG*TRI*NN];     // partial Grams
__device__ float    g_Ginv[TRI*NN];           // inv Gram, layout [tri][j]
__device__ float    g_sigma[NN];
__device__ float    g_sc[8];                  // alpha, c, lamda, mu, sigma0

// ---------------- scalar prep: alpha via closed-form chi2 CDFs ----------------
// chi2_cdf(x,1) = erf(sqrt(x/2)); chi2_cdf(x,3) = erf(sqrt(x/2)) - sqrt(2/pi)*sqrt(x)*exp(-x/2)
__global__ void k_scalars(const float* c, const float* lam, const float* mu, const float* sg){
  double cd = (double)c[0];
  double t1 = erf(cd * 0.7071067811865475244);
  double chi3 = t1 - sqrt(2.0/M_PI)*cd*exp(-0.5*cd*cd);
  double alpha = 0.5*cd*cd*(1.0 - t1) + 0.5*chi3;
  g_sc[0] = (float)alpha;
  g_sc[1] = c[0];
  g_sc[2] = lam[0];
  g_sc[3] = mu[0];
  g_sc[4] = sg[0];
}

__global__ void k_copyUV(const float* __restrict__ U, const float* __restrict__ V){
  int t = blockIdx.x*256 + threadIdx.x;
  if (t < MM*RNK){ g_U[t] = U[t]; g_V[t] = V[t]; }
}

// ---------------- transpose X -> g_XT (32x32 tiles) ----------------
__global__ void k_transpose(const float* __restrict__ src){
  __shared__ float tile[32][33];
  int bx = blockIdx.x*32, by = blockIdx.y*32;
  int tx = threadIdx.x, ty = threadIdx.y;
  #pragma unroll
  for (int yo=0; yo<32; yo+=8)
    tile[ty+yo][tx] = src[(size_t)(by+ty+yo)*NN + bx+tx];
  __syncthreads();
  #pragma unroll
  for (int yo=0; yo<32; yo+=8)
    g_XT[(size_t)(bx+ty+yo)*NN + by+tx] = tile[tx][ty+yo];
}

// ---------------- pack mask bits (ballot) ----------------
__global__ void k_pack(const float* __restrict__ Xin, int which){
  int e = blockIdx.x*256 + threadIdx.x;
  const float* src = which ? g_XT : Xin;
  unsigned w = __ballot_sync(0xffffffffu, src[e] != 0.0f);
  if ((threadIdx.x & 31) == 0){
    if (which) g_mbT[e>>5] = w; else g_mb[e>>5] = w;
  }
}

// which==0: col nobs (from mbT rows); which==1: row nobs (from mb rows)
__global__ void k_nobs(int which){
  int j = blockIdx.x*256 + threadIdx.x;
  const unsigned* b = which ? g_mb : g_mbT;
  int s = 0;
  #pragma unroll 8
  for (int w=0; w<NWRD; w++) s += __popc(b[j*NWRD + w]);
  if (which) g_nobs_row[j] = (float)s; else g_nobs_col[j] = (float)s;
}

// ---------------- per-regression masked Gram (packed lower 55) ----------------
// step=0 (V-step): D = U [4096x10] row-major; step=1 (U-step): D[i,k] = V[k*NN+i]
// grid (16, GSEG), block (32,8). Thread owns one regression j fully within its segment.
__global__ void __launch_bounds__(256) k_gram(int step){
  __shared__ float sD[CH*RNK];
  const float* D       = step ? g_V : g_U;
  const int sDr        = step ? 1   : RNK;
  const int sDc        = step ? NN  : 1;
  const unsigned* bits = step ? g_mbT : g_mb;
  int tx = threadIdx.x, ty = threadIdx.y;
  int tid = ty*32 + tx;
  int wq = blockIdx.x*8 + ty;         // mask word index = column group of 32
  int seg = blockIdx.y;
  float acc[TRI];
  #pragma unroll
  for (int t=0;t<TRI;t++) acc[t]=0.f;
  const int rps = MM/GSEG;
  const int base = seg*rps;
  for (int c0=base; c0<base+rps; c0+=CH){
    __syncthreads();
    for (int t=tid; t<CH*RNK; t+=256){
      int k = t/CH, rr = t - k*CH;
      sD[rr*RNK + k] = D[(c0+rr)*sDr + k*sDc];
    }
    __syncthreads();
    for (int rr=0; rr<CH; rr++){
      unsigned w = bits[(c0+rr)*NWRD + wq];        // uniform per warp
      float m = (float)((w >> tx) & 1u);
      const float* dp = &sD[rr*RNK];
      float d[RNK];
      #pragma unroll
      for (int k=0;k<RNK;k++) d[k]=dp[k];
      #pragma unroll
      for (int k=0;k<RNK;k++){
        float dmk = d[k]*m;
        #pragma unroll
        for (int l=0;l<=k;l++)
          acc[k*(k+1)/2+l] = fmaf(dmk, d[l], acc[k*(k+1)/2+l]);
      }
    }
  }
  int j = wq*32 + tx;
  float* out = g_Gpart + seg*(TRI*NN);
  #pragma unroll
  for (int t=0;t<TRI;t++) out[t*NN + j] = acc[t];
}

// ---------------- 10x10 SPD inverse via packed in-place Cholesky ----------------
__global__ void __launch_bounds__(128) k_ginv(){
  int j = blockIdx.x*128 + threadIdx.x;
  float A[TRI];
  #pragma unroll
  for (int t=0;t<TRI;t++){
    float s=0.f;
    #pragma unroll
    for (int seg=0;seg<GSEG;seg++) s += g_Gpart[seg*(TRI*NN) + t*NN + j];
    A[t]=s;
  }
  // in-place Cholesky: A <- L (packed lower)
  #pragma unroll
  for (int k=0;k<RNK;k++){
    float s = A[k*(k+1)/2+k];
    #pragma unroll
    for (int m2=0;m2<k;m2++){ float v=A[k*(k+1)/2+m2]; s -= v*v; }
    float lkk = sqrtf(s);
    A[k*(k+1)/2+k]=lkk;
    float inv = 1.0f/lkk;
    #pragma unroll
    for (int i=k+1;i<RNK;i++){
      float t = A[i*(i+1)/2+k];
      #pragma unroll
      for (int m2=0;m2<k;m2++) t -= A[i*(i+1)/2+m2]*A[k*(k+1)/2+m2];
      A[i*(i+1)/2+k]=t*inv;
    }
  }
  // in-place lower-triangular inverse: A <- L^{-1}
  #pragma unroll
  for (int jj=0;jj<RNK;jj++){
    A[jj*(jj+1)/2+jj] = 1.0f/A[jj*(jj+1)/2+jj];
    #pragma unroll
    for (int i=jj+1;i<RNK;i++){
      float s=0.f;
      #pragma unroll
      for (int m2=jj;m2<i;m2++) s += A[i*(i+1)/2+m2]*A[m2*(m2+1)/2+jj];
      A[i*(i+1)/2+jj] = -s / A[i*(i+1)/2+i];
    }
  }
  // Ginv = Linv^T * Linv (packed lower), stored transposed [tri][j] for coalescing
  #pragma unroll
  for (int a=0;a<RNK;a++){
    #pragma unroll
    for (int b=0;b<=a;b++){
      float s=0.f;
      #pragma unroll
      for (int m2=a;m2<RNK;m2++) s += A[m2*(m2+1)/2+a]*A[m2*(m2+1)/2+b];
      g_Ginv[(a*(a+1)/2+b)*NN + j] = s;
    }
  }
}

// ---------------- IRLS pass A: psi^2 column sums -> tau -> sigma update ----------------
// grid 128, block (32,8): 32 regressions/block, 8 threads reduce over rows.
__global__ void __launch_bounds__(256) k_iterA(const float* __restrict__ Xin, int step, int iter0){
  __shared__ float sD[CH*RNK];
  __shared__ float sS[8][32];
  const float* Y    = step ? g_XT : Xin;
  const float* D    = step ? g_V : g_U;
  const int sDr     = step ? 1   : RNK;
  const int sDc     = step ? NN  : 1;
  const float* beta = step ? g_U : g_V;
  const int sBj     = step ? RNK : 1;
  const int sBk     = step ? 1   : NN;
  const float* nobs = step ? g_nobs_row : g_nobs_col;
  int tx=threadIdx.x, ty=threadIdx.y, tid=ty*32+tx;
  int j = blockIdx.x*32 + tx;
  float b[RNK];
  #pragma unroll
  for (int k=0;k<RNK;k++) b[k] = beta[j*sBj + k*sBk];
  float cc = g_sc[1];
  float sig = iter0 ? g_sc[4] : g_sigma[j];
  float invs = 1.0f/sig;
  float S = 0.f;
  for (int c0=0; c0<MM; c0+=CH){
    __syncthreads();
    for (int t=tid; t<CH*RNK; t+=256){
      int k=t/CH, rr=t-k*CH;
      sD[rr*RNK+k] = D[(c0+rr)*sDr + k*sDc];
    }
    __syncthreads();
    #pragma unroll 4
    for (int rr=ty; rr<CH; rr+=8){
      float x = Y[(size_t)(c0+rr)*NN + j];
      const float* dp = &sD[rr*RNK];
      float r = x;
      #pragma unroll
      for (int k=0;k<RNK;k++) r -= dp[k]*b[k];
      r = (x==0.f) ? 0.f : r;                 // mask = (X != 0)
      float psi = fminf(cc, fmaxf(-cc, r*invs));
      S = fmaf(psi, psi, S);
    }
  }
  sS[ty][tx] = S;
  __syncthreads();
  if (ty==0){
    float tot = 0.f;
    #pragma unroll
    for (int t=0;t<8;t++) tot += sS[t][tx];
    float tau = sqrtf(tot) / sqrtf(2.0f*nobs[j]*g_sc[0]);
    g_sigma[j] = sig * powf(tau, g_sc[2]);
  }
}

// ---------------- IRLS pass B: rhs = D^T clip(R,+-c*sigma), delta = Ginv*rhs, beta += mu*delta
__global__ void __launch_bounds__(256) k_iterB(const float* __restrict__ Xin, int step){
  __shared__ float sD[CH*RNK];
  __shared__ float sR[RNK][8][32];
  const float* Y    = step ? g_XT : Xin;
  const float* D    = step ? g_V : g_U;
  const int sDr     = step ? 1   : RNK;
  const int sDc     = step ? NN  : 1;
  float* beta       = step ? g_U : g_V;
  const int sBj     = step ? RNK : 1;
  const int sBk     = step ? 1   : NN;
  int tx=threadIdx.x, ty=threadIdx.y, tid=ty*32+tx;
  int j = blockIdx.x*32 + tx;
  float b[RNK];
  #pragma unroll
  for (int k=0;k<RNK;k++) b[k] = beta[j*sBj + k*sBk];
  float sig = g_sigma[j];
  float cs = g_sc[1]*sig;
  float rhs[RNK];
  #pragma unroll
  for (int k=0;k<RNK;k++) rhs[k]=0.f;
  for (int c0=0; c0<MM; c0+=CH){
    __syncthreads();
    for (int t=tid; t<CH*RNK; t+=256){
      int k=t/CH, rr=t-k*CH;
      sD[rr*RNK+k] = D[(c0+rr)*sDr + k*sDc];
    }
    __syncthreads();
    #pragma unroll 4
    for (int rr=ty; rr<CH; rr+=8){
      float x = Y[(size_t)(c0+rr)*NN + j];
      const float* dp = &sD[rr*RNK];
      float r = x;
      #pragma unroll
      for (int k=0;k<RNK;k++) r -= dp[k]*b[k];
      r = (x==0.f) ? 0.f : r;
      float w = fminf(cs, fmaxf(-cs, r));       // psi2 * sigma
      #pragma unroll
      for (int k=0;k<RNK;k++) rhs[k] = fmaf(dp[k], w, rhs[k]);
    }
  }
  #pragma unroll
  for (int k=0;k<RNK;k++) sR[k][ty][tx] = rhs[k];
  __syncthreads();
  if (ty==0){
    float rr2[RNK];
    #pragma unroll
    for (int k=0;k<RNK;k++){
      float s=0.f;
      #pragma unroll
      for (int t=0;t<8;t++) s += sR[k][t][tx];
      rr2[k]=s;
    }
    float muv = g_sc[3];
    #pragma unroll
    for (int a=0;a<RNK;a++){
      float s=0.f;
      #pragma unroll
      for (int q=0;q<RNK;q++){
        int t = (a>=q) ? (a*(a+1)/2+q) : (q*(q+1)/2+a);
        s = fmaf(g_Ginv[t*NN + j], rr2[q], s);
      }
      beta[j*sBj + a*sBk] += muv*s;
    }
  }
}

// ---------------- final output: U @ V ----------------
__global__ void k_out(float* __restrict__ out){
  int e = blockIdx.x*256 + threadIdx.x;
  int i = e >> 12;
  int j = e & (NN-1);
  float s = 0.f;
  #pragma unroll
  for (int k=0;k<RNK;k++) s = fmaf(g_U[i*RNK+k], g_V[k*NN+j], s);
  out[e] = s;
}

// ---------------- host driver (graph-capturable: kernel launches only) ----------------
extern "C" void kernel_launch(void* const* d_in, const int* in_sizes, int n_in,
                              void* d_out, int out_size){
  // robust input mapping: X is the MM*NN-sized input; U then V are the 40960-sized;
  // scalars (size 1) in declared order: c, lamda, mu, sigma
  const float *U=0, *V=0, *X=0, *pc=0, *plam=0, *pmu=0, *psg=0;
  int nuv=0, nsc=0;
  for (int i=0;i<n_in;i++){
    if (in_sizes[i] == MM*NN) X = (const float*)d_in[i];
    else if (in_sizes[i] == MM*RNK){ if (nuv==0) U=(const float*)d_in[i]; else V=(const float*)d_in[i]; nuv++; }
    else if (in_sizes[i] == 1){
      if      (nsc==0) pc  =(const float*)d_in[i];
      else if (nsc==1) plam=(const float*)d_in[i];
      else if (nsc==2) pmu =(const float*)d_in[i];
      else if (nsc==3) psg =(const float*)d_in[i];
      nsc++;
    }
  }
  float* out = (float*)d_out;

  k_scalars<<<1,1>>>(pc, plam, pmu, psg);
  k_copyUV<<<(MM*RNK + 255)/256, 256>>>(U, V);
  {
    dim3 g(NN/32, MM/32), b(32,8);
    k_transpose<<<g,b>>>(X);
  }
  k_pack<<<(MM*NN)/256, 256>>>(X, 0);
  k_pack<<<(MM*NN)/256, 256>>>(X, 1);   // reads g_XT internally
  k_nobs<<<NN/256, 256>>>(0);           // col nobs
  k_nobs<<<MM/256, 256>>>(1);           // row nobs

  dim3 gb(16, GSEG), bb(32,8);
  dim3 ib(32,8);
  for (int layer=0; layer<N_LAYERS; layer++){
    for (int step=0; step<2; step++){   // 0: V-step, 1: U-step
      k_gram<<<gb, bb>>>(step);
      k_ginv<<<NN/128, 128>>>();
      for (int it=0; it<HUB_ITERS; it++){
        k_iterA<<<NN/32, ib>>>(X, step, it==0 ? 1 : 0);
        k_iterB<<<NN/32, ib>>>(X, step);
      }
    }
  }
  k_out<<<(MM*NN)/256, 256>>>(out);
}

// round 5
// speedup vs baseline: 2.0773x; 2.0773x over previous
#include <cuda_runtime.h>
#include <math.h>

#ifndef M_PI
#define M_PI 3.14159265358979323846
#endif

#define MM 4096
#define NN 4096
#define RNK 10
#define TRI 55         // 10*11/2 packed lower triangle
#define NWRD 128       // 4096/32 mask words per row
#define GSEG 16        // row segments for gram
#define GROWS (MM/GSEG)     // 256 rows per gram block
#define ASEG 8         // row segments for IRLS passes
#define AROWS (MM/ASEG)     // 512 rows per IRLS block
#define N_LAYERS 3
#define HUB_ITERS 2

typedef unsigned long long u64;

// ---------------- device scratch (static: no allocation APIs) ----------------
__device__ float    g_U[MM*RNK];
__device__ float    g_V[RNK*NN];
__device__ float    g_XT[(size_t)MM*NN];          // 64 MB
__device__ unsigned g_mb [MM*NWRD];               // mask bits of X (row-major)
__device__ unsigned g_mbT[NN*NWRD];               // mask bits of X^T
__device__ float    g_nobs_col[NN];
__device__ float    g_nobs_row[MM];
__device__ float    g_Gpart[GSEG*TRI*NN];         // 14.4 MB partial Grams
__device__ float    g_G[TRI*NN];                  // reduced Gram
__device__ float    g_Ginv[TRI*NN];               // inv Gram, layout [tri][j]
__device__ float    g_Spart[ASEG*NN];             // psi^2 partials
__device__ float    g_Rpart[ASEG*RNK*NN];         // rhs partials [seg][k][j]
__device__ float    g_sigma[NN];
__device__ float    g_sc[8];                      // alpha, c, lamda, mu, sigma0

// ---------------- f32x2 packed helpers (PTX-only; 2x fp32 FMA throughput) ----
__device__ __forceinline__ u64 pk(float a, float b){
  u64 r; asm("mov.b64 %0, {%1, %2};" : "=l"(r) : "f"(a), "f"(b)); return r;
}
__device__ __forceinline__ void upk(u64 v, float& a, float& b){
  asm("mov.b64 {%0, %1}, %2;" : "=f"(a), "=f"(b) : "l"(v));
}
__device__ __forceinline__ u64 fma2(u64 a, u64 b, u64 c){
  u64 d; asm("fma.rn.f32x2 %0, %1, %2, %3;" : "=l"(d) : "l"(a), "l"(b), "l"(c)); return d;
}
__device__ __forceinline__ u64 mul2(u64 a, u64 b){
  u64 d; asm("mul.rn.f32x2 %0, %1, %2;" : "=l"(d) : "l"(a), "l"(b)); return d;
}

// ---------------- scalar prep: alpha via closed-form chi2 CDFs ----------------
__global__ void k_scalars(const float* c, const float* lam, const float* mu, const float* sg){
  double cd = (double)c[0];
  double t1 = erf(cd * 0.7071067811865475244);
  double chi3 = t1 - sqrt(2.0/M_PI)*cd*exp(-0.5*cd*cd);
  double alpha = 0.5*cd*cd*(1.0 - t1) + 0.5*chi3;
  g_sc[0] = (float)alpha;
  g_sc[1] = c[0];
  g_sc[2] = lam[0];
  g_sc[3] = mu[0];
  g_sc[4] = sg[0];
}

__global__ void k_copyUV(const float* __restrict__ U, const float* __restrict__ V){
  int t = blockIdx.x*256 + threadIdx.x;
  if (t < MM*RNK){ g_U[t] = U[t]; g_V[t] = V[t]; }
}

// -------- fused transpose X -> g_XT + bitpack of both orientations ----------
__global__ void k_transpose(const float* __restrict__ src){
  __shared__ float tile[32][33];
  int bx = blockIdx.x*32, by = blockIdx.y*32;
  int tx = threadIdx.x, ty = threadIdx.y;
  #pragma unroll
  for (int yo=0; yo<32; yo+=8){
    float v = src[(size_t)(by+ty+yo)*NN + bx+tx];
    tile[ty+yo][tx] = v;
    unsigned w = __ballot_sync(0xffffffffu, v != 0.0f);
    if (tx==0) g_mb[(by+ty+yo)*NWRD + (bx>>5)] = w;
  }
  __syncthreads();
  #pragma unroll
  for (int yo=0; yo<32; yo+=8){
    float v = tile[tx][ty+yo];
    g_XT[(size_t)(bx+ty+yo)*NN + by+tx] = v;
    unsigned w = __ballot_sync(0xffffffffu, v != 0.0f);
    if (tx==0) g_mbT[(bx+ty+yo)*NWRD + (by>>5)] = w;
  }
}

// ---------------- nobs (both orientations in one launch) ----------------
__global__ void k_nobs(){
  int t = blockIdx.x*256 + threadIdx.x;   // [0, 8192)
  int j = t & (NN-1);
  const unsigned* b = (t < NN) ? g_mbT : g_mb;
  int s = 0;
  #pragma unroll 8
  for (int w=0; w<NWRD; w++) s += __popc(b[j*NWRD + w]);
  if (t < NN) g_nobs_col[j] = (float)s; else g_nobs_row[j] = (float)s;
}

// --------- per-regression masked Gram, packed lower 55, f32x2 row pairs ------
// grid (32, GSEG), block (32,4). Thread owns regression j within its segment.
__global__ void __launch_bounds__(128) k_gram(int step){
  __shared__ u64 sD[(GROWS/2)*RNK];   // packed row pairs, 10 KB
  const float* D       = step ? g_V : g_U;
  const int sDr        = step ? 1   : RNK;
  const int sDc        = step ? NN  : 1;
  const unsigned* bits = step ? g_mbT : g_mb;
  int tx = threadIdx.x, ty = threadIdx.y;
  int tid = ty*32 + tx;
  int wq = blockIdx.x*4 + ty;          // mask word index [0,128)
  int base = blockIdx.y * GROWS;
  for (int t = tid; t < (GROWS/2)*RNK; t += 128){
    int k = t >> 7, rp = t & 127;
    int r0 = base + 2*rp;
    sD[rp*RNK + k] = pk(D[r0*sDr + k*sDc], D[(r0+1)*sDr + k*sDc]);
  }
  __syncthreads();
  u64 acc[TRI];
  u64 z = pk(0.f, 0.f);
  #pragma unroll
  for (int t=0;t<TRI;t++) acc[t]=z;
  const unsigned* bp = bits + (size_t)base*NWRD + wq;
  for (int rp=0; rp<GROWS/2; rp++){
    unsigned w0 = bp[0];
    unsigned w1 = bp[NWRD];
    bp += 2*NWRD;
    u64 mm = pk((float)((w0>>tx)&1u), (float)((w1>>tx)&1u));
    const u64* dp = &sD[rp*RNK];
    u64 d[RNK];
    #pragma unroll
    for (int k=0;k<RNK;k++) d[k]=dp[k];
    #pragma unroll
    for (int k=0;k<RNK;k++){
      u64 dm = mul2(d[k], mm);
      #pragma unroll
      for (int l=0;l<=k;l++)
        acc[k*(k+1)/2+l] = fma2(dm, d[l], acc[k*(k+1)/2+l]);
    }
  }
  int j = wq*32 + tx;
  float* out = g_Gpart + blockIdx.y*(TRI*NN);
  #pragma unroll
  for (int t=0;t<TRI;t++){
    float a,b; upk(acc[t],a,b);
    out[t*NN + j] = a + b;
  }
}

// ---------------- reduce Gram partials ----------------
__global__ void k_gred(){
  int e = blockIdx.x*256 + threadIdx.x;   // [0, TRI*NN)
  float s = 0.f;
  #pragma unroll
  for (int seg=0; seg<GSEG; seg++) s += g_Gpart[seg*(TRI*NN) + e];
  g_G[e] = s;
}

// ---------------- 10x10 SPD inverse via packed in-place Cholesky ----------------
__global__ void __launch_bounds__(256) k_ginv(){
  int j = blockIdx.x*256 + threadIdx.x;
  float A[TRI];
  #pragma unroll
  for (int t=0;t<TRI;t++) A[t] = g_G[t*NN + j];
  #pragma unroll
  for (int k=0;k<RNK;k++){
    float s = A[k*(k+1)/2+k];
    #pragma unroll
    for (int m2=0;m2<k;m2++){ float v=A[k*(k+1)/2+m2]; s -= v*v; }
    float lkk = sqrtf(s);
    A[k*(k+1)/2+k]=lkk;
    float inv = 1.0f/lkk;
    #pragma unroll
    for (int i=k+1;i<RNK;i++){
      float t = A[i*(i+1)/2+k];
      #pragma unroll
      for (int m2=0;m2<k;m2++) t -= A[i*(i+1)/2+m2]*A[k*(k+1)/2+m2];
      A[i*(i+1)/2+k]=t*inv;
    }
  }
  #pragma unroll
  for (int jj=0;jj<RNK;jj++){
    A[jj*(jj+1)/2+jj] = 1.0f/A[jj*(jj+1)/2+jj];
    #pragma unroll
    for (int i=jj+1;i<RNK;i++){
      float s=0.f;
      #pragma unroll
      for (int m2=jj;m2<i;m2++) s += A[i*(i+1)/2+m2]*A[m2*(m2+1)/2+jj];
      A[i*(i+1)/2+jj] = -s / A[i*(i+1)/2+i];
    }
  }
  #pragma unroll
  for (int a=0;a<RNK;a++){
    #pragma unroll
    for (int b=0;b<=a;b++){
      float s=0.f;
      #pragma unroll
      for (int m2=a;m2<RNK;m2++) s += A[m2*(m2+1)/2+a]*A[m2*(m2+1)/2+b];
      g_Ginv[(a*(a+1)/2+b)*NN + j] = s;
    }
  }
}

// ---------------- IRLS pass A (segmented): psi^2 partial sums ----------------
// grid (128, ASEG), block (32,8)
__global__ void __launch_bounds__(256) k_psiA(const float* __restrict__ Xin, int step, int it0){
  __shared__ u64 sD[(AROWS/2)*RNK];   // 20 KB
  __shared__ float sS[8][33];
  const float* Y    = step ? g_XT : Xin;
  const float* D    = step ? g_V : g_U;
  const int sDr     = step ? 1   : RNK;
  const int sDc     = step ? NN  : 1;
  const float* beta = step ? g_U : g_V;
  const int sBj     = step ? RNK : 1;
  const int sBk     = step ? 1   : NN;
  int tx=threadIdx.x, ty=threadIdx.y, tid=ty*32+tx;
  int j = blockIdx.x*32 + tx;
  int base = blockIdx.y * AROWS;
  for (int t = tid; t < (AROWS/2)*RNK; t += 256){
    int k = t >> 8, rp = t & 255;
    int r0 = base + 2*rp;
    sD[rp*RNK + k] = pk(D[r0*sDr + k*sDc], D[(r0+1)*sDr + k*sDc]);
  }
  __syncthreads();
  u64 nb[RNK];
  #pragma unroll
  for (int k=0;k<RNK;k++){ float b = -beta[j*sBj + k*sBk]; nb[k] = pk(b,b); }
  float cc = g_sc[1];
  float sig = it0 ? g_sc[4] : g_sigma[j];
  float invs = 1.0f/sig;
  float S = 0.f;
  #pragma unroll 2
  for (int rp = ty; rp < AROWS/2; rp += 8){
    int r0 = base + 2*rp;
    float x0 = Y[(size_t)r0*NN + j];
    float x1 = Y[(size_t)(r0+1)*NN + j];
    const u64* dp = &sD[rp*RNK];
    u64 rr = pk(x0, x1);
    #pragma unroll
    for (int k=0;k<RNK;k++) rr = fma2(dp[k], nb[k], rr);
    float r0f, r1f; upk(rr, r0f, r1f);
    r0f = (x0==0.f) ? 0.f : r0f;
    r1f = (x1==0.f) ? 0.f : r1f;
    float p0 = fminf(cc, fmaxf(-cc, r0f*invs));
    float p1 = fminf(cc, fmaxf(-cc, r1f*invs));
    S = fmaf(p0,p0,S);
    S = fmaf(p1,p1,S);
  }
  sS[ty][tx] = S;
  __syncthreads();
  if (ty==0){
    float tot = 0.f;
    #pragma unroll
    for (int t=0;t<8;t++) tot += sS[t][tx];
    g_Spart[blockIdx.y*NN + j] = tot;
  }
}

// ---------------- sigma update ----------------
__global__ void k_sigma(int step, int it0){
  int j = blockIdx.x*256 + threadIdx.x;
  const float* nobs = step ? g_nobs_row : g_nobs_col;
  float tot = 0.f;
  #pragma unroll
  for (int s=0;s<ASEG;s++) tot += g_Spart[s*NN + j];
  float sig = it0 ? g_sc[4] : g_sigma[j];
  float tau = sqrtf(tot) / sqrtf(2.0f*nobs[j]*g_sc[0]);
  g_sigma[j] = sig * powf(tau, g_sc[2]);
}

// ---------------- IRLS pass B (segmented): rhs partials ----------------
__global__ void __launch_bounds__(256) k_rhsB(const float* __restrict__ Xin, int step){
  __shared__ u64 sD[(AROWS/2)*RNK];   // 20 KB
  __shared__ float sR[RNK][8][33];    // 10.3 KB
  const float* Y    = step ? g_XT : Xin;
  const float* D    = step ? g_V : g_U;
  const int sDr     = step ? 1   : RNK;
  const int sDc     = step ? NN  : 1;
  const float* beta = step ? g_U : g_V;
  const int sBj     = step ? RNK : 1;
  const int sBk     = step ? 1   : NN;
  int tx=threadIdx.x, ty=threadIdx.y, tid=ty*32+tx;
  int j = blockIdx.x*32 + tx;
  int base = blockIdx.y * AROWS;
  for (int t = tid; t < (AROWS/2)*RNK; t += 256){
    int k = t >> 8, rp = t & 255;
    int r0 = base + 2*rp;
    sD[rp*RNK + k] = pk(D[r0*sDr + k*sDc], D[(r0+1)*sDr + k*sDc]);
  }
  __syncthreads();
  u64 nb[RNK];
  #pragma unroll
  for (int k=0;k<RNK;k++){ float b = -beta[j*sBj + k*sBk]; nb[k] = pk(b,b); }
  float cs = g_sc[1]*g_sigma[j];
  u64 rhs[RNK];
  u64 z = pk(0.f,0.f);
  #pragma unroll
  for (int k=0;k<RNK;k++) rhs[k]=z;
  #pragma unroll 2
  for (int rp = ty; rp < AROWS/2; rp += 8){
    int r0 = base + 2*rp;
    float x0 = Y[(size_t)r0*NN + j];
    float x1 = Y[(size_t)(r0+1)*NN + j];
    const u64* dp = &sD[rp*RNK];
    u64 d[RNK];
    #pragma unroll
    for (int k=0;k<RNK;k++) d[k]=dp[k];
    u64 rr = pk(x0, x1);
    #pragma unroll
    for (int k=0;k<RNK;k++) rr = fma2(d[k], nb[k], rr);
    float r0f, r1f; upk(rr, r0f, r1f);
    r0f = (x0==0.f) ? 0.f : r0f;
    r1f = (x1==0.f) ? 0.f : r1f;
    float w0 = fminf(cs, fmaxf(-cs, r0f));
    float w1 = fminf(cs, fmaxf(-cs, r1f));
    u64 ww = pk(w0, w1);
    #pragma unroll
    for (int k=0;k<RNK;k++) rhs[k] = fma2(d[k], ww, rhs[k]);
  }
  #pragma unroll
  for (int k=0;k<RNK;k++){
    float a,b; upk(rhs[k],a,b);
    sR[k][ty][tx] = a + b;
  }
  __syncthreads();
  if (ty==0){
    #pragma unroll
    for (int k=0;k<RNK;k++){
      float s=0.f;
      #pragma unroll
      for (int t=0;t<8;t++) s += sR[k][t][tx];
      g_Rpart[(blockIdx.y*RNK + k)*NN + j] = s;
    }
  }
}

// ---------------- beta update: delta = Ginv * rhs, beta += mu*delta ----------
__global__ void k_beta(int step){
  int j = blockIdx.x*256 + threadIdx.x;
  float* beta = step ? g_U : g_V;
  const int sBj = step ? RNK : 1;
  const int sBk = step ? 1   : NN;
  float rr[RNK];
  #pragma unroll
  for (int k=0;k<RNK;k++){
    float s=0.f;
    #pragma unroll
    for (int seg=0;seg<ASEG;seg++) s += g_Rpart[(seg*RNK + k)*NN + j];
    rr[k]=s;
  }
  float muv = g_sc[3];
  #pragma unroll
  for (int a=0;a<RNK;a++){
    float s=0.f;
    #pragma unroll
    for (int q=0;q<RNK;q++){
      int t = (a>=q) ? (a*(a+1)/2+q) : (q*(q+1)/2+a);
      s = fmaf(g_Ginv[t*NN + j], rr[q], s);
    }
    beta[j*sBj + a*sBk] += muv*s;
  }
}

// ---------------- final output: U @ V (float4 over columns) ----------------
__global__ void k_out(float* __restrict__ out){
  int e = blockIdx.x*256 + threadIdx.x;   // group of 4 outputs
  int i = e >> 10;
  int j4 = (e & 1023) * 4;
  float4 s = make_float4(0.f,0.f,0.f,0.f);
  #pragma unroll
  for (int k=0;k<RNK;k++){
    float u = g_U[i*RNK+k];
    float4 v = *reinterpret_cast<const float4*>(&g_V[k*NN + j4]);
    s.x = fmaf(u, v.x, s.x);
    s.y = fmaf(u, v.y, s.y);
    s.z = fmaf(u, v.z, s.z);
    s.w = fmaf(u, v.w, s.w);
  }
  reinterpret_cast<float4*>(out)[e] = s;
}

// ---------------- host driver (graph-capturable: kernel launches only) ----------------
extern "C" void kernel_launch(void* const* d_in, const int* in_sizes, int n_in,
                              void* d_out, int out_size){
  const float *U=0, *V=0, *X=0, *pc=0, *plam=0, *pmu=0, *psg=0;
  int nuv=0, nsc=0;
  for (int i=0;i<n_in;i++){
    if (in_sizes[i] == MM*NN) X = (const float*)d_in[i];
    else if (in_sizes[i] == MM*RNK){ if (nuv==0) U=(const float*)d_in[i]; else V=(const float*)d_in[i]; nuv++; }
    else if (in_sizes[i] == 1){
      if      (nsc==0) pc  =(const float*)d_in[i];
      else if (nsc==1) plam=(const float*)d_in[i];
      else if (nsc==2) pmu =(const float*)d_in[i];
      else if (nsc==3) psg =(const float*)d_in[i];
      nsc++;
    }
  }
  float* out = (float*)d_out;

  k_scalars<<<1,1>>>(pc, plam, pmu, psg);
  k_copyUV<<<(MM*RNK + 255)/256, 256>>>(U, V);
  {
    dim3 g(NN/32, MM/32), b(32,8);
    k_transpose<<<g,b>>>(X);
  }
  k_nobs<<<(2*NN)/256, 256>>>();

  dim3 ggrid(32, GSEG), gblk(32,4);
  dim3 igrid(NN/32, ASEG), iblk(32,8);
  for (int layer=0; layer<N_LAYERS; layer++){
    for (int step=0; step<2; step++){   // 0: V-step, 1: U-step
      k_gram<<<ggrid, gblk>>>(step);
      k_gred<<<(TRI*NN)/256, 256>>>();
      k_ginv<<<NN/256, 256>>>();
      for (int it=0; it<HUB_ITERS; it++){
        int it0 = (it==0) ? 1 : 0;
        k_psiA<<<igrid, iblk>>>(X, step, it0);
        k_sigma<<<NN/256, 256>>>(step, it0);
        k_rhsB<<<igrid, iblk>>>(X, step);
        k_beta<<<NN/256, 256>>>(step);
      }
    }
  }
  k_out<<<(MM*NN/4)/256, 256>>>(out);
}

// round 7
// speedup vs baseline: 2.1415x; 1.0309x over previous
#include <cuda_runtime.h>
#include <math.h>

#ifndef M_PI
#define M_PI 3.14159265358979323846
#endif

#define MM 4096
#define NN 4096
#define RNK 10
#define TRI 55          // 10*11/2 packed lower triangle
#define NWRD 128        // 4096/32 mask words per row
#define GSEG 32         // row segments for gram
#define GROWS (MM/GSEG) // 128 rows per gram block
#define ASEG 16         // row segments for IRLS passes
#define AROWS (MM/ASEG) // 256 rows per IRLS block
#define N_LAYERS 3

typedef unsigned long long u64;

// ---------------- device scratch (static: no allocation APIs) ----------------
__device__ float    g_U[MM*RNK];
__device__ float    g_V[RNK*NN];
__device__ float    g_XT[(size_t)MM*NN];          // 64 MB
__device__ unsigned g_mb [MM*NWRD];               // mask bits of X (row-major)
__device__ unsigned g_mbT[NN*NWRD];               // mask bits of X^T
__device__ float    g_nobs_col[NN];
__device__ float    g_nobs_row[MM];
__device__ float    g_Gpart[GSEG*TRI*NN];         // 28.8 MB partial Grams
__device__ float    g_G[TRI*NN];                  // reduced Gram
__device__ float    g_Ginv[TRI*NN];               // inv Gram, layout [tri][j]
__device__ float    g_Spart[ASEG*NN];             // psi^2 partials
__device__ float    g_Rpart0[ASEG*RNK*NN];        // rhs partials iter0 [seg][k][j]
__device__ float    g_Rpart1[ASEG*RNK*NN];        // rhs partials iter1
__device__ float    g_sigma[NN];
__device__ float    g_sc[8];                      // alpha, c, lamda, mu, sigma0

// ---------------- f32x2 packed helpers ----------------
__device__ __forceinline__ u64 pk(float a, float b){
  u64 r; asm("mov.b64 %0, {%1, %2};" : "=l"(r) : "f"(a), "f"(b)); return r;
}
__device__ __forceinline__ void upk(u64 v, float& a, float& b){
  asm("mov.b64 {%0, %1}, %2;" : "=f"(a), "=f"(b) : "l"(v));
}
__device__ __forceinline__ u64 fma2(u64 a, u64 b, u64 c){
  u64 d; asm("fma.rn.f32x2 %0, %1, %2, %3;" : "=l"(d) : "l"(a), "l"(b), "l"(c)); return d;
}
__device__ __forceinline__ u64 mul2(u64 a, u64 b){
  u64 d; asm("mul.rn.f32x2 %0, %1, %2;" : "=l"(d) : "l"(a), "l"(b)); return d;
}

// packed triangle index for (a,q) symmetric access
__device__ __forceinline__ int triat(int a, int q){
  return (a>=q) ? (a*(a+1)/2+q) : (q*(q+1)/2+a);
}

// ---------------- scalar prep ----------------
__global__ void k_scalars(const float* c, const float* lam, const float* mu, const float* sg){
  double cd = (double)c[0];
  double t1 = erf(cd * 0.7071067811865475244);
  double chi3 = t1 - sqrt(2.0/M_PI)*cd*exp(-0.5*cd*cd);
  double alpha = 0.5*cd*cd*(1.0 - t1) + 0.5*chi3;
  g_sc[0] = (float)alpha;
  g_sc[1] = c[0];
  g_sc[2] = lam[0];
  g_sc[3] = mu[0];
  g_sc[4] = sg[0];
}

__global__ void k_copyUV(const float* __restrict__ U, const float* __restrict__ V){
  int t = blockIdx.x*256 + threadIdx.x;
  if (t < MM*RNK){ g_U[t] = U[t]; g_V[t] = V[t]; }
}

// -------- fused transpose X -> g_XT + bitpack of both orientations ----------
__global__ void k_transpose(const float* __restrict__ src){
  __shared__ float tile[32][33];
  int bx = blockIdx.x*32, by = blockIdx.y*32;
  int tx = threadIdx.x, ty = threadIdx.y;
  #pragma unroll
  for (int yo=0; yo<32; yo+=8){
    float v = src[(size_t)(by+ty+yo)*NN + bx+tx];
    tile[ty+yo][tx] = v;
    unsigned w = __ballot_sync(0xffffffffu, v != 0.0f);
    if (tx==0) g_mb[(by+ty+yo)*NWRD + (bx>>5)] = w;
  }
  __syncthreads();
  #pragma unroll
  for (int yo=0; yo<32; yo+=8){
    float v = tile[tx][ty+yo];
    g_XT[(size_t)(bx+ty+yo)*NN + by+tx] = v;
    unsigned w = __ballot_sync(0xffffffffu, v != 0.0f);
    if (tx==0) g_mbT[(bx+ty+yo)*NWRD + (by>>5)] = w;
  }
}

// ---------------- nobs: warp-per-row, uint4 loads ----------------
__global__ void k_nobs(){
  int t = blockIdx.x*8 + threadIdx.y;     // [0, 8192)
  int lane = threadIdx.x;
  int j = t & (NN-1);
  const unsigned* b = (t < NN) ? g_mbT : g_mb;
  uint4 w = *reinterpret_cast<const uint4*>(&b[j*NWRD + lane*4]);
  int s = __popc(w.x)+__popc(w.y)+__popc(w.z)+__popc(w.w);
  #pragma unroll
  for (int o=16;o;o>>=1) s += __shfl_xor_sync(0xffffffffu, s, o);
  if (lane==0){
    if (t < NN) g_nobs_col[j] = (float)s; else g_nobs_row[j] = (float)s;
  }
}

// --------- per-regression masked Gram, packed lower 55, f32x2 row pairs ------
// grid (32, GSEG), block (32,4). Thread owns regression j within its segment.
__global__ void __launch_bounds__(128) k_gram(int step){
  __shared__ u64 sD[(GROWS/2)*RNK];   // 5 KB packed row pairs
  const float* D       = step ? g_V : g_U;
  const int sDr        = step ? 1   : RNK;
  const int sDc        = step ? NN  : 1;
  const unsigned* bits = step ? g_mbT : g_mb;
  int tx = threadIdx.x, ty = threadIdx.y;
  int tid = ty*32 + tx;
  int wq = blockIdx.x*4 + ty;          // mask word index [0,128)
  int base = blockIdx.y * GROWS;
  for (int t = tid; t < (GROWS/2)*RNK; t += 128){
    int k = t / (GROWS/2), rp = t % (GROWS/2);
    int r0 = base + 2*rp;
    sD[rp*RNK + k] = pk(D[r0*sDr + k*sDc], D[(r0+1)*sDr + k*sDc]);
  }
  __syncthreads();
  u64 acc[TRI];
  u64 z = pk(0.f, 0.f);
  #pragma unroll
  for (int t=0;t<TRI;t++) acc[t]=z;
  const unsigned* bp = bits + (size_t)base*NWRD + wq;
  #pragma unroll 2
  for (int rp=0; rp<GROWS/2; rp++){
    unsigned w0 = bp[0];
    unsigned w1 = bp[NWRD];
    bp += 2*NWRD;
    u64 mm = pk((float)((w0>>tx)&1u), (float)((w1>>tx)&1u));
    const u64* dp = &sD[rp*RNK];
    u64 d[RNK];
    #pragma unroll
    for (int k=0;k<RNK;k++) d[k]=dp[k];
    #pragma unroll
    for (int k=0;k<RNK;k++){
      u64 dm = mul2(d[k], mm);
      #pragma unroll
      for (int l=0;l<=k;l++)
        acc[k*(k+1)/2+l] = fma2(dm, d[l], acc[k*(k+1)/2+l]);
    }
  }
  int j = wq*32 + tx;
  float* out = g_Gpart + blockIdx.y*(TRI*NN);
  #pragma unroll
  for (int t=0;t<TRI;t++){
    float a,b; upk(acc[t],a,b);
    out[t*NN + j] = a + b;
  }
}

// ---------------- reduce Gram partials ----------------
__global__ void k_gred(){
  int e = blockIdx.x*256 + threadIdx.x;   // [0, TRI*NN)
  float s = 0.f;
  #pragma unroll
  for (int seg=0; seg<GSEG; seg++) s += g_Gpart[seg*(TRI*NN) + e];
  g_G[e] = s;
}

// ---------------- 10x10 SPD inverse via packed in-place Cholesky ----------------
__global__ void __launch_bounds__(64) k_ginv(){
  int j = blockIdx.x*64 + threadIdx.x;
  float A[TRI];
  #pragma unroll
  for (int t=0;t<TRI;t++) A[t] = g_G[t*NN + j];
  #pragma unroll
  for (int k=0;k<RNK;k++){
    float s = A[k*(k+1)/2+k];
    #pragma unroll
    for (int m2=0;m2<k;m2++){ float v=A[k*(k+1)/2+m2]; s -= v*v; }
    float lkk = sqrtf(s);
    A[k*(k+1)/2+k]=lkk;
    float inv = 1.0f/lkk;
    #pragma unroll
    for (int i=k+1;i<RNK;i++){
      float t = A[i*(i+1)/2+k];
      #pragma unroll
      for (int m2=0;m2<k;m2++) t -= A[i*(i+1)/2+m2]*A[k*(k+1)/2+m2];
      A[i*(i+1)/2+k]=t*inv;
    }
  }
  #pragma unroll
  for (int jj=0;jj<RNK;jj++){
    A[jj*(jj+1)/2+jj] = 1.0f/A[jj*(jj+1)/2+jj];
    #pragma unroll
    for (int i=jj+1;i<RNK;i++){
      float s=0.f;
      #pragma unroll
      for (int m2=jj;m2<i;m2++) s += A[i*(i+1)/2+m2]*A[m2*(m2+1)/2+jj];
      A[i*(i+1)/2+jj] = -s / A[i*(i+1)/2+i];
    }
  }
  #pragma unroll
  for (int a=0;a<RNK;a++){
    #pragma unroll
    for (int b=0;b<=a;b++){
      float s=0.f;
      #pragma unroll
      for (int m2=a;m2<RNK;m2++) s += A[m2*(m2+1)/2+a]*A[m2*(m2+1)/2+b];
      g_Ginv[(a*(a+1)/2+b)*NN + j] = s;
    }
  }
}

// ---- shared beta load + optional inline iter-1 update (beta1 = beta0 + mu*Ginv*rhs0)
__device__ __forceinline__ void load_beta_pair(const float* beta, int sBj, int sBk,
                                               int jA, int jB, int it,
                                               float* bA, float* bB){
  #pragma unroll
  for (int k=0;k<RNK;k++){
    bA[k] = beta[jA*sBj + k*sBk];
    bB[k] = beta[jB*sBj + k*sBk];
  }
  if (it){
    float rA[RNK], rB[RNK];
    #pragma unroll
    for (int k=0;k<RNK;k++){
      float sA=0.f, sB=0.f;
      #pragma unroll
      for (int s=0;s<ASEG;s++){
        sA += g_Rpart0[(s*RNK+k)*NN + jA];
        sB += g_Rpart0[(s*RNK+k)*NN + jB];
      }
      rA[k]=sA; rB[k]=sB;
    }
    float muv = g_sc[3];
    #pragma unroll
    for (int a=0;a<RNK;a++){
      float dA=0.f, dB=0.f;
      #pragma unroll
      for (int q=0;q<RNK;q++){
        int t = triat(a,q);
        dA = fmaf(g_Ginv[t*NN + jA], rA[q], dA);
        dB = fmaf(g_Ginv[t*NN + jB], rB[q], dB);
      }
      bA[a] += muv*dA;
      bB[a] += muv*dB;
    }
  }
}

// ---------------- IRLS pass A: psi^2 partials (column pairs) ----------------
// grid (NN/64, ASEG), block (32,8)
__global__ void __launch_bounds__(256) k_psiA(const float* __restrict__ Xin, int step, int it){
  __shared__ u64 sD[256*RNK];     // 20 KB, dup-packed rows
  __shared__ u64 sS[8][33];
  const float* Y    = step ? g_XT : Xin;
  const float* D    = step ? g_V : g_U;
  const int sDr     = step ? 1   : RNK;
  const int sDc     = step ? NN  : 1;
  const float* beta = step ? g_U : g_V;
  const int sBj     = step ? RNK : 1;
  const int sBk     = step ? 1   : NN;
  int tx=threadIdx.x, ty=threadIdx.y, tid=ty*32+tx;
  int jp = blockIdx.x*32 + tx;
  int jA = 2*jp, jB = jA+1;
  int base = blockIdx.y * AROWS;

  float bA[RNK], bB[RNK];
  load_beta_pair(beta, sBj, sBk, jA, jB, it, bA, bB);
  u64 nb[RNK];
  #pragma unroll
  for (int k=0;k<RNK;k++) nb[k] = pk(-bA[k], -bB[k]);

  float cc = g_sc[1];
  float sigA = it ? g_sigma[jA] : g_sc[4];
  float sigB = it ? g_sigma[jB] : g_sc[4];
  float iA = 1.0f/sigA, iB = 1.0f/sigB;
  u64 S2 = pk(0.f,0.f);

  for (int c0=0; c0<AROWS; c0+=256){
    __syncthreads();
    for (int t=tid; t<256*RNK; t+=256){
      int k = t >> 8, r = t & 255;
      float v = D[(base+c0+r)*sDr + k*sDc];
      sD[r*RNK+k] = pk(v,v);
    }
    __syncthreads();
    #pragma unroll 4
    for (int r=ty; r<256; r+=8){
      float2 x = *reinterpret_cast<const float2*>(&Y[(size_t)(base+c0+r)*NN + jA]);
      const u64* dp = &sD[r*RNK];
      u64 rr = pk(x.x, x.y);
      #pragma unroll
      for (int k=0;k<RNK;k++) rr = fma2(dp[k], nb[k], rr);
      float r0,r1; upk(rr,r0,r1);
      r0 = (x.x==0.f) ? 0.f : r0;
      r1 = (x.y==0.f) ? 0.f : r1;
      float p0 = fminf(cc, fmaxf(-cc, r0*iA));
      float p1 = fminf(cc, fmaxf(-cc, r1*iB));
      u64 pp = pk(p0,p1);
      S2 = fma2(pp, pp, S2);
    }
  }
  sS[ty][tx] = S2;
  __syncthreads();
  if (ty==0){
    float tA=0.f, tB=0.f;
    #pragma unroll
    for (int t=0;t<8;t++){ float a,b; upk(sS[t][tx],a,b); tA+=a; tB+=b; }
    g_Spart[blockIdx.y*NN + jA] = tA;
    g_Spart[blockIdx.y*NN + jB] = tB;
  }
}

// ---------------- IRLS pass B: sigma inline + rhs partials ----------------
__global__ void __launch_bounds__(256) k_rhsB(const float* __restrict__ Xin, int step, int it){
  __shared__ u64 sD[256*RNK];     // 20 KB
  __shared__ u64 sR[RNK][8][33];  // 20.6 KB
  const float* Y    = step ? g_XT : Xin;
  const float* D    = step ? g_V : g_U;
  const int sDr     = step ? 1   : RNK;
  const int sDc     = step ? NN  : 1;
  const float* beta = step ? g_U : g_V;
  const int sBj     = step ? RNK : 1;
  const int sBk     = step ? 1   : NN;
  const float* nobs = step ? g_nobs_row : g_nobs_col;
  int tx=threadIdx.x, ty=threadIdx.y, tid=ty*32+tx;
  int jp = blockIdx.x*32 + tx;
  int jA = 2*jp, jB = jA+1;
  int base = blockIdx.y * AROWS;

  float bA[RNK], bB[RNK];
  load_beta_pair(beta, sBj, sBk, jA, jB, it, bA, bB);
  u64 nb[RNK];
  #pragma unroll
  for (int k=0;k<RNK;k++) nb[k] = pk(-bA[k], -bB[k]);

  // inline sigma update: sigma_new = sigma_prev * tau^lamda
  float SA=0.f, SB=0.f;
  #pragma unroll
  for (int s=0;s<ASEG;s++){
    SA += g_Spart[s*NN + jA];
    SB += g_Spart[s*NN + jB];
  }
  float al = g_sc[0], lam = g_sc[2], cc = g_sc[1];
  float spA = it ? g_sigma[jA] : g_sc[4];
  float spB = it ? g_sigma[jB] : g_sc[4];
  float tauA = sqrtf(SA) / sqrtf(2.0f*nobs[jA]*al);
  float tauB = sqrtf(SB) / sqrtf(2.0f*nobs[jB]*al);
  float sigA = spA * powf(tauA, lam);
  float sigB = spB * powf(tauB, lam);
  if (it==0 && blockIdx.y==0 && ty==0){
    g_sigma[jA] = sigA; g_sigma[jB] = sigB;
  }
  float csA = cc*sigA, csB = cc*sigB;

  u64 rhs[RNK];
  u64 z = pk(0.f,0.f);
  #pragma unroll
  for (int k=0;k<RNK;k++) rhs[k]=z;

  for (int c0=0; c0<AROWS; c0+=256){
    __syncthreads();
    for (int t=tid; t<256*RNK; t+=256){
      int k = t >> 8, r = t & 255;
      float v = D[(base+c0+r)*sDr + k*sDc];
      sD[r*RNK+k] = pk(v,v);
    }
    __syncthreads();
    #pragma unroll 4
    for (int r=ty; r<256; r+=8){
      float2 x = *reinterpret_cast<const float2*>(&Y[(size_t)(base+c0+r)*NN + jA]);
      const u64* dp = &sD[r*RNK];
      u64 d[RNK];
      #pragma unroll
      for (int k=0;k<RNK;k++) d[k]=dp[k];
      u64 rr = pk(x.x, x.y);
      #pragma unroll
      for (int k=0;k<RNK;k++) rr = fma2(d[k], nb[k], rr);
      float r0,r1; upk(rr,r0,r1);
      r0 = (x.x==0.f) ? 0.f : r0;
      r1 = (x.y==0.f) ? 0.f : r1;
      float w0 = fminf(csA, fmaxf(-csA, r0));
      float w1 = fminf(csB, fmaxf(-csB, r1));
      u64 ww = pk(w0, w1);
      #pragma unroll
      for (int k=0;k<RNK;k++) rhs[k] = fma2(d[k], ww, rhs[k]);
    }
  }
  #pragma unroll
  for (int k=0;k<RNK;k++) sR[k][ty][tx] = rhs[k];
  __syncthreads();
  if (ty==0){
    float* Rout = it ? g_Rpart1 : g_Rpart0;
    #pragma unroll
    for (int k=0;k<RNK;k++){
      float tA=0.f, tB=0.f;
      #pragma unroll
      for (int t=0;t<8;t++){ float a,b; upk(sR[k][t][tx],a,b); tA+=a; tB+=b; }
      Rout[(blockIdx.y*RNK + k)*NN + jA] = tA;
      Rout[(blockIdx.y*RNK + k)*NN + jB] = tB;
    }
  }
}

// -------- final beta for the step: beta2 = beta0 + mu*Ginv*(rhs0 + rhs1) -----
__global__ void __launch_bounds__(128) k_beta2(int step){
  int j = blockIdx.x*128 + threadIdx.x;
  float* beta = step ? g_U : g_V;
  const int sBj = step ? RNK : 1;
  const int sBk = step ? 1   : NN;
  float rr[RNK];
  #pragma unroll
  for (int k=0;k<RNK;k++){
    float s=0.f;
    #pragma unroll
    for (int seg=0;seg<ASEG;seg++){
      s += g_Rpart0[(seg*RNK + k)*NN + j];
      s += g_Rpart1[(seg*RNK + k)*NN + j];
    }
    rr[k]=s;
  }
  float muv = g_sc[3];
  #pragma unroll
  for (int a=0;a<RNK;a++){
    float s=0.f;
    #pragma unroll
    for (int q=0;q<RNK;q++)
      s = fmaf(g_Ginv[triat(a,q)*NN + j], rr[q], s);
    beta[j*sBj + a*sBk] += muv*s;
  }
}

// ---------------- final output: U @ V (float4 over columns) ----------------
__global__ void k_out(float* __restrict__ out){
  int e = blockIdx.x*256 + threadIdx.x;   // group of 4 outputs
  int i = e >> 10;
  int j4 = (e & 1023) * 4;
  float4 s = make_float4(0.f,0.f,0.f,0.f);
  #pragma unroll
  for (int k=0;k<RNK;k++){
    float u = g_U[i*RNK+k];
    float4 v = *reinterpret_cast<const float4*>(&g_V[k*NN + j4]);
    s.x = fmaf(u, v.x, s.x);
    s.y = fmaf(u, v.y, s.y);
    s.z = fmaf(u, v.z, s.z);
    s.w = fmaf(u, v.w, s.w);
  }
  reinterpret_cast<float4*>(out)[e] = s;
}

// ---------------- host driver (graph-capturable: kernel launches only) ----------------
extern "C" void kernel_launch(void* const* d_in, const int* in_sizes, int n_in,
                              void* d_out, int out_size){
  const float *U=0, *V=0, *X=0, *pc=0, *plam=0, *pmu=0, *psg=0;
  int nuv=0, nsc=0;
  for (int i=0;i<n_in;i++){
    if (in_sizes[i] == MM*NN) X = (const float*)d_in[i];
    else if (in_sizes[i] == MM*RNK){ if (nuv==0) U=(const float*)d_in[i]; else V=(const float*)d_in[i]; nuv++; }
    else if (in_sizes[i] == 1){
      if      (nsc==0) pc  =(const float*)d_in[i];
      else if (nsc==1) plam=(const float*)d_in[i];
      else if (nsc==2) pmu =(const float*)d_in[i];
      else if (nsc==3) psg =(const float*)d_in[i];
      nsc++;
    }
  }
  float* out = (float*)d_out;

  k_scalars<<<1,1>>>(pc, plam, pmu, psg);                        // launch 0
  k_copyUV<<<(MM*RNK + 255)/256, 256>>>(U, V);                   // launch 1
  {
    dim3 g(NN/32, MM/32), b(32,8);
    k_transpose<<<g,b>>>(X);                                     // launch 2
  }

  dim3 ggrid(32, GSEG), gblk(32,4);
  dim3 igrid(NN/64, ASEG), iblk(32,8);
  dim3 ngrid(8192/8), nblk(32,8);
  for (int layer=0; layer<N_LAYERS; layer++){
    for (int step=0; step<2; step++){   // 0: V-step, 1: U-step
      k_gram<<<ggrid, gblk>>>(step);                             // first = launch 3 (profiled)
      if (layer==0 && step==0) k_nobs<<<ngrid, nblk>>>();
      k_gred<<<(TRI*NN)/256, 256>>>();
      k_ginv<<<NN/64, 64>>>();
      for (int it=0; it<2; it++){
        k_psiA<<<igrid, iblk>>>(X, step, it);
        k_rhsB<<<igrid, iblk>>>(X, step, it);
      }
      k_beta2<<<NN/128, 128>>>(step);
    }
  }
  k_out<<<(MM*NN/4)/256, 256>>>(out);
}

// round 8
// speedup vs baseline: 2.5765x; 1.2031x over previous
#include <cuda_runtime.h>
#include <math.h>

#ifndef M_PI
#define M_PI 3.14159265358979323846
#endif

#define MM 4096
#define NN 4096
#define RNK 10
#define TRI 55          // 10*11/2 packed lower triangle
#define NWRD 128        // 4096/32 mask words per row
#define GSEG 32         // row segments for gram
#define GROWS (MM/GSEG) // 128 rows per gram block
#define ASEG 32         // row segments for IRLS passes
#define AROWS (MM/ASEG) // 128 rows per IRLS block
#define N_LAYERS 3

typedef unsigned long long u64;

// ---------------- device scratch (static: no allocation APIs) ----------------
__device__ float    g_U[MM*RNK];
__device__ float    g_V[RNK*NN];
__device__ float    g_XT[(size_t)MM*NN];          // 64 MB
__device__ unsigned g_mb [MM*NWRD];               // mask bits of X (row-major)
__device__ unsigned g_mbT[NN*NWRD];               // mask bits of X^T
__device__ float    g_nobs_col[NN];
__device__ float    g_nobs_row[MM];
__device__ float    g_Gpart[GSEG*TRI*NN];         // 28.8 MB partial Grams
__device__ float    g_G[TRI*NN];                  // reduced Gram
__device__ float    g_Ginv[TRI*NN];               // inv Gram, layout [tri][j]
__device__ float    g_Spart[ASEG*NN];             // psi^2 partials
__device__ float    g_Rpart0[ASEG*RNK*NN];        // rhs partials iter0 [seg][k][j]
__device__ float    g_Rpart1[ASEG*RNK*NN];        // rhs partials iter1
__device__ float    g_beta1[RNK*NN];              // beta after iter0, layout [k][j]
__device__ float    g_sigma[NN];
__device__ float    g_sc[8];                      // alpha, c, lamda, mu, sigma0

// ---------------- f32x2 packed helpers ----------------
__device__ __forceinline__ u64 pk(float a, float b){
  u64 r; asm("mov.b64 %0, {%1, %2};" : "=l"(r) : "f"(a), "f"(b)); return r;
}
__device__ __forceinline__ void upk(u64 v, float& a, float& b){
  asm("mov.b64 {%0, %1}, %2;" : "=f"(a), "=f"(b) : "l"(v));
}
__device__ __forceinline__ u64 fma2(u64 a, u64 b, u64 c){
  u64 d; asm("fma.rn.f32x2 %0, %1, %2, %3;" : "=l"(d) : "l"(a), "l"(b), "l"(c)); return d;
}
__device__ __forceinline__ u64 mul2(u64 a, u64 b){
  u64 d; asm("mul.rn.f32x2 %0, %1, %2;" : "=l"(d) : "l"(a), "l"(b)); return d;
}

__device__ __forceinline__ int triat(int a, int q){
  return (a>=q) ? (a*(a+1)/2+q) : (q*(q+1)/2+a);
}

// ---------------- scalar prep ----------------
__global__ void k_scalars(const float* c, const float* lam, const float* mu, const float* sg){
  double cd = (double)c[0];
  double t1 = erf(cd * 0.7071067811865475244);
  double chi3 = t1 - sqrt(2.0/M_PI)*cd*exp(-0.5*cd*cd);
  double alpha = 0.5*cd*cd*(1.0 - t1) + 0.5*chi3;
  g_sc[0] = (float)alpha;
  g_sc[1] = c[0];
  g_sc[2] = lam[0];
  g_sc[3] = mu[0];
  g_sc[4] = sg[0];
}

__global__ void k_copyUV(const float* __restrict__ U, const float* __restrict__ V){
  int t = blockIdx.x*256 + threadIdx.x;
  if (t < MM*RNK){ g_U[t] = U[t]; g_V[t] = V[t]; }
}

// -------- fused transpose X -> g_XT + bitpack of both orientations ----------
__global__ void k_transpose(const float* __restrict__ src){
  __shared__ float tile[32][33];
  int bx = blockIdx.x*32, by = blockIdx.y*32;
  int tx = threadIdx.x, ty = threadIdx.y;
  #pragma unroll
  for (int yo=0; yo<32; yo+=8){
    float v = src[(size_t)(by+ty+yo)*NN + bx+tx];
    tile[ty+yo][tx] = v;
    unsigned w = __ballot_sync(0xffffffffu, v != 0.0f);
    if (tx==0) g_mb[(by+ty+yo)*NWRD + (bx>>5)] = w;
  }
  __syncthreads();
  #pragma unroll
  for (int yo=0; yo<32; yo+=8){
    float v = tile[tx][ty+yo];
    g_XT[(size_t)(bx+ty+yo)*NN + by+tx] = v;
    unsigned w = __ballot_sync(0xffffffffu, v != 0.0f);
    if (tx==0) g_mbT[(bx+ty+yo)*NWRD + (by>>5)] = w;
  }
}

// ---------------- nobs: warp-per-row, uint4 loads ----------------
__global__ void k_nobs(){
  int t = blockIdx.x*8 + threadIdx.y;     // [0, 8192)
  int lane = threadIdx.x;
  int j = t & (NN-1);
  const unsigned* b = (t < NN) ? g_mbT : g_mb;
  uint4 w = *reinterpret_cast<const uint4*>(&b[j*NWRD + lane*4]);
  int s = __popc(w.x)+__popc(w.y)+__popc(w.z)+__popc(w.w);
  #pragma unroll
  for (int o=16;o;o>>=1) s += __shfl_xor_sync(0xffffffffu, s, o);
  if (lane==0){
    if (t < NN) g_nobs_col[j] = (float)s; else g_nobs_row[j] = (float)s;
  }
}

// --------- masked Gram, triangle split 2-way across threads ------------------
// grid (64, GSEG), block (32,4). wq = bx*2 + (ty>>1); half = ty&1.
// half 0: tri rows k=0..6 (28 elems); half 1: k=7..9 (27 elems).
__global__ void __launch_bounds__(128) k_gram(int step){
  __shared__ u64 sD[(GROWS/2)*RNK];   // 5 KB packed row pairs
  const float* D       = step ? g_V : g_U;
  const int sDr        = step ? 1   : RNK;
  const int sDc        = step ? NN  : 1;
  const unsigned* bits = step ? g_mbT : g_mb;
  int tx = threadIdx.x, ty = threadIdx.y;
  int tid = ty*32 + tx;
  int wq = blockIdx.x*2 + (ty>>1);     // [0,128)
  int half = ty & 1;
  int base = blockIdx.y * GROWS;
  for (int t = tid; t < (GROWS/2)*RNK; t += 128){
    int k = t >> 6, rp = t & 63;       // GROWS/2 = 64
    int r0 = base + 2*rp;
    sD[rp*RNK + k] = pk(D[r0*sDr + k*sDc], D[(r0+1)*sDr + k*sDc]);
  }
  __syncthreads();
  int j = wq*32 + tx;
  float* out = g_Gpart + blockIdx.y*(TRI*NN);
  const unsigned* bp = bits + (size_t)base*NWRD + wq;
  u64 z = pk(0.f, 0.f);
  if (half == 0){
    u64 acc[28];
    #pragma unroll
    for (int t=0;t<28;t++) acc[t]=z;
    #pragma unroll 2
    for (int rp=0; rp<GROWS/2; rp++){
      unsigned w0 = bp[0];
      unsigned w1 = bp[NWRD];
      bp += 2*NWRD;
      u64 mm = pk((float)((w0>>tx)&1u), (float)((w1>>tx)&1u));
      const u64* dp = &sD[rp*RNK];
      u64 d[7];
      #pragma unroll
      for (int k=0;k<7;k++) d[k]=dp[k];
      #pragma unroll
      for (int k=0;k<7;k++){
        u64 dm = mul2(d[k], mm);
        #pragma unroll
        for (int l=0;l<=k;l++)
          acc[k*(k+1)/2+l] = fma2(dm, d[l], acc[k*(k+1)/2+l]);
      }
    }
    #pragma unroll
    for (int t=0;t<28;t++){
      float a,b; upk(acc[t],a,b);
      out[t*NN + j] = a + b;
    }
  } else {
    u64 acc[27];
    #pragma unroll
    for (int t=0;t<27;t++) acc[t]=z;
    #pragma unroll 2
    for (int rp=0; rp<GROWS/2; rp++){
      unsigned w0 = bp[0];
      unsigned w1 = bp[NWRD];
      bp += 2*NWRD;
      u64 mm = pk((float)((w0>>tx)&1u), (float)((w1>>tx)&1u));
      const u64* dp = &sD[rp*RNK];
      u64 d[RNK];
      #pragma unroll
      for (int k=0;k<RNK;k++) d[k]=dp[k];
      #pragma unroll
      for (int k=7;k<RNK;k++){
        u64 dm = mul2(d[k], mm);
        #pragma unroll
        for (int l=0;l<=k;l++)
          acc[k*(k+1)/2+l-28] = fma2(dm, d[l], acc[k*(k+1)/2+l-28]);
      }
    }
    #pragma unroll
    for (int t=0;t<27;t++){
      float a,b; upk(acc[t],a,b);
      out[(t+28)*NN + j] = a + b;
    }
  }
}

// ---------------- reduce Gram partials ----------------
__global__ void k_gred(){
  int e = blockIdx.x*256 + threadIdx.x;   // [0, TRI*NN)
  float s = 0.f;
  #pragma unroll
  for (int seg=0; seg<GSEG; seg++) s += g_Gpart[seg*(TRI*NN) + e];
  g_G[e] = s;
}

// ---------------- 10x10 SPD inverse via packed in-place Cholesky ----------------
__global__ void __launch_bounds__(64) k_ginv(){
  int j = blockIdx.x*64 + threadIdx.x;
  float A[TRI];
  #pragma unroll
  for (int t=0;t<TRI;t++) A[t] = g_G[t*NN + j];
  #pragma unroll
  for (int k=0;k<RNK;k++){
    float s = A[k*(k+1)/2+k];
    #pragma unroll
    for (int m2=0;m2<k;m2++){ float v=A[k*(k+1)/2+m2]; s -= v*v; }
    float lkk = sqrtf(s);
    A[k*(k+1)/2+k]=lkk;
    float inv = 1.0f/lkk;
    #pragma unroll
    for (int i=k+1;i<RNK;i++){
      float t = A[i*(i+1)/2+k];
      #pragma unroll
      for (int m2=0;m2<k;m2++) t -= A[i*(i+1)/2+m2]*A[k*(k+1)/2+m2];
      A[i*(i+1)/2+k]=t*inv;
    }
  }
  #pragma unroll
  for (int jj=0;jj<RNK;jj++){
    A[jj*(jj+1)/2+jj] = 1.0f/A[jj*(jj+1)/2+jj];
    #pragma unroll
    for (int i=jj+1;i<RNK;i++){
      float s=0.f;
      #pragma unroll
      for (int m2=jj;m2<i;m2++) s += A[i*(i+1)/2+m2]*A[m2*(m2+1)/2+jj];
      A[i*(i+1)/2+jj] = -s / A[i*(i+1)/2+i];
    }
  }
  #pragma unroll
  for (int a=0;a<RNK;a++){
    #pragma unroll
    for (int b=0;b<=a;b++){
      float s=0.f;
      #pragma unroll
      for (int m2=a;m2<RNK;m2++) s += A[m2*(m2+1)/2+a]*A[m2*(m2+1)/2+b];
      g_Ginv[(a*(a+1)/2+b)*NN + j] = s;
    }
  }
}

// ---------------- IRLS pass A: psi^2 partials ----------------
// grid (NN/64, ASEG), block (64,4). One column per thread.
__global__ void __launch_bounds__(256) k_psiA(const float* __restrict__ Xin, int step, int it){
  __shared__ float sD[AROWS*RNK];   // 5 KB
  __shared__ float sS[4][65];
  const float* Y    = step ? g_XT : Xin;
  const float* D    = step ? g_V : g_U;
  const int sDr     = step ? 1   : RNK;
  const int sDc     = step ? NN  : 1;
  const float* beta = step ? g_U : g_V;
  const int sBj     = step ? RNK : 1;
  const int sBk     = step ? 1   : NN;
  int tx=threadIdx.x, ty=threadIdx.y, tid=ty*64+tx;
  int j = blockIdx.x*64 + tx;
  int base = blockIdx.y * AROWS;
  for (int t=tid; t<AROWS*RNK; t+=256){
    int k = t >> 7, r = t & (AROWS-1);
    sD[r*RNK+k] = D[(base+r)*sDr + k*sDc];
  }
  __syncthreads();
  float nb[RNK];
  if (it){
    #pragma unroll
    for (int k=0;k<RNK;k++) nb[k] = -g_beta1[k*NN + j];
  } else {
    #pragma unroll
    for (int k=0;k<RNK;k++) nb[k] = -beta[j*sBj + k*sBk];
  }
  float cc = g_sc[1];
  float sig = it ? g_sigma[j] : g_sc[4];
  float invs = 1.0f/sig;
  float S = 0.f;
  #pragma unroll 8
  for (int r=ty; r<AROWS; r+=4){
    float x = Y[(size_t)(base+r)*NN + j];
    const float* dp = &sD[r*RNK];
    float rr = x;
    #pragma unroll
    for (int k=0;k<RNK;k++) rr = fmaf(dp[k], nb[k], rr);
    rr = (x==0.f) ? 0.f : rr;
    float p = fminf(cc, fmaxf(-cc, rr*invs));
    S = fmaf(p,p,S);
  }
  sS[ty][tx] = S;
  __syncthreads();
  if (ty==0){
    float tot = sS[0][tx]+sS[1][tx]+sS[2][tx]+sS[3][tx];
    g_Spart[blockIdx.y*NN + j] = tot;
  }
}

// ---------------- IRLS pass B: inline sigma + rhs partials ----------------
__global__ void __launch_bounds__(256) k_rhsB(const float* __restrict__ Xin, int step, int it){
  __shared__ float sD[AROWS*RNK];   // 5 KB
  __shared__ float sR[RNK][4][65];  // 10.4 KB
  const float* Y    = step ? g_XT : Xin;
  const float* D    = step ? g_V : g_U;
  const int sDr     = step ? 1   : RNK;
  const int sDc     = step ? NN  : 1;
  const float* beta = step ? g_U : g_V;
  const int sBj     = step ? RNK : 1;
  const int sBk     = step ? 1   : NN;
  const float* nobs = step ? g_nobs_row : g_nobs_col;
  int tx=threadIdx.x, ty=threadIdx.y, tid=ty*64+tx;
  int j = blockIdx.x*64 + tx;
  int base = blockIdx.y * AROWS;
  for (int t=tid; t<AROWS*RNK; t+=256){
    int k = t >> 7, r = t & (AROWS-1);
    sD[r*RNK+k] = D[(base+r)*sDr + k*sDc];
  }
  __syncthreads();
  float nb[RNK];
  if (it){
    #pragma unroll
    for (int k=0;k<RNK;k++) nb[k] = -g_beta1[k*NN + j];
  } else {
    #pragma unroll
    for (int k=0;k<RNK;k++) nb[k] = -beta[j*sBj + k*sBk];
  }
  // inline sigma update: sigma_new = sigma_prev * tau^lamda
  float SA=0.f;
  #pragma unroll
  for (int s=0;s<ASEG;s++) SA += g_Spart[s*NN + j];
  float sp = it ? g_sigma[j] : g_sc[4];
  float tau = sqrtf(SA) / sqrtf(2.0f*nobs[j]*g_sc[0]);
  float sig = sp * powf(tau, g_sc[2]);
  if (it==0 && blockIdx.y==0 && ty==0) g_sigma[j] = sig;
  float cs = g_sc[1]*sig;

  float rhs[RNK];
  #pragma unroll
  for (int k=0;k<RNK;k++) rhs[k]=0.f;
  #pragma unroll 4
  for (int r=ty; r<AROWS; r+=4){
    float x = Y[(size_t)(base+r)*NN + j];
    const float* dp = &sD[r*RNK];
    float rr = x;
    #pragma unroll
    for (int k=0;k<RNK;k++) rr = fmaf(dp[k], nb[k], rr);
    rr = (x==0.f) ? 0.f : rr;
    float w = fminf(cs, fmaxf(-cs, rr));
    #pragma unroll
    for (int k=0;k<RNK;k++) rhs[k] = fmaf(dp[k], w, rhs[k]);
  }
  #pragma unroll
  for (int k=0;k<RNK;k++) sR[k][ty][tx] = rhs[k];
  __syncthreads();
  if (ty==0){
    float* Rout = it ? g_Rpart1 : g_Rpart0;
    #pragma unroll
    for (int k=0;k<RNK;k++){
      float s = sR[k][0][tx]+sR[k][1][tx]+sR[k][2][tx]+sR[k][3][tx];
      Rout[(blockIdx.y*RNK + k)*NN + j] = s;
    }
  }
}

// -------- beta1 = beta0 + mu*Ginv*rhs0 (materialized once, layout [k][j]) ----
__global__ void __launch_bounds__(128) k_beta1(int step){
  int j = blockIdx.x*128 + threadIdx.x;
  const float* beta = step ? g_U : g_V;
  const int sBj = step ? RNK : 1;
  const int sBk = step ? 1   : NN;
  float rr[RNK];
  #pragma unroll
  for (int k=0;k<RNK;k++){
    float s=0.f;
    #pragma unroll
    for (int seg=0;seg<ASEG;seg++) s += g_Rpart0[(seg*RNK + k)*NN + j];
    rr[k]=s;
  }
  float muv = g_sc[3];
  #pragma unroll
  for (int a=0;a<RNK;a++){
    float s=0.f;
    #pragma unroll
    for (int q=0;q<RNK;q++)
      s = fmaf(g_Ginv[triat(a,q)*NN + j], rr[q], s);
    g_beta1[a*NN + j] = beta[j*sBj + a*sBk] + muv*s;
  }
}

// -------- final beta for the step: beta2 = beta1 + mu*Ginv*rhs1 --------------
__global__ void __launch_bounds__(128) k_beta2(int step){
  int j = blockIdx.x*128 + threadIdx.x;
  float* beta = step ? g_U : g_V;
  const int sBj = step ? RNK : 1;
  const int sBk = step ? 1   : NN;
  float rr[RNK];
  #pragma unroll
  for (int k=0;k<RNK;k++){
    float s=0.f;
    #pragma unroll
    for (int seg=0;seg<ASEG;seg++) s += g_Rpart1[(seg*RNK + k)*NN + j];
    rr[k]=s;
  }
  float muv = g_sc[3];
  #pragma unroll
  for (int a=0;a<RNK;a++){
    float s=0.f;
    #pragma unroll
    for (int q=0;q<RNK;q++)
      s = fmaf(g_Ginv[triat(a,q)*NN + j], rr[q], s);
    beta[j*sBj + a*sBk] = g_beta1[a*NN + j] + muv*s;
  }
}

// ---------------- final output: U @ V (float4 over columns) ----------------
__global__ void k_out(float* __restrict__ out){
  int e = blockIdx.x*256 + threadIdx.x;   // group of 4 outputs
  int i = e >> 10;
  int j4 = (e & 1023) * 4;
  float4 s = make_float4(0.f,0.f,0.f,0.f);
  #pragma unroll
  for (int k=0;k<RNK;k++){
    float u = g_U[i*RNK+k];
    float4 v = *reinterpret_cast<const float4*>(&g_V[k*NN + j4]);
    s.x = fmaf(u, v.x, s.x);
    s.y = fmaf(u, v.y, s.y);
    s.z = fmaf(u, v.z, s.z);
    s.w = fmaf(u, v.w, s.w);
  }
  reinterpret_cast<float4*>(out)[e] = s;
}

// ---------------- host driver (graph-capturable: kernel launches only) ----------------
extern "C" void kernel_launch(void* const* d_in, const int* in_sizes, int n_in,
                              void* d_out, int out_size){
  const float *U=0, *V=0, *X=0, *pc=0, *plam=0, *pmu=0, *psg=0;
  int nuv=0, nsc=0;
  for (int i=0;i<n_in;i++){
    if (in_sizes[i] == MM*NN) X = (const float*)d_in[i];
    else if (in_sizes[i] == MM*RNK){ if (nuv==0) U=(const float*)d_in[i]; else V=(const float*)d_in[i]; nuv++; }
    else if (in_sizes[i] == 1){
      if      (nsc==0) pc  =(const float*)d_in[i];
      else if (nsc==1) plam=(const float*)d_in[i];
      else if (nsc==2) pmu =(const float*)d_in[i];
      else if (nsc==3) psg =(const float*)d_in[i];
      nsc++;
    }
  }
  float* out = (float*)d_out;

  k_scalars<<<1,1>>>(pc, plam, pmu, psg);                        // launch 0
  k_copyUV<<<(MM*RNK + 255)/256, 256>>>(U, V);                   // launch 1
  {
    dim3 g(NN/32, MM/32), b(32,8);
    k_transpose<<<g,b>>>(X);                                     // launch 2
  }

  dim3 ggrid(64, GSEG), gblk(32,4);
  dim3 igrid(NN/64, ASEG), iblk(64,4);
  dim3 ngrid(8192/8), nblk(32,8);
  for (int layer=0; layer<N_LAYERS; layer++){
    for (int step=0; step<2; step++){   // 0: V-step, 1: U-step
      k_gram<<<ggrid, gblk>>>(step);                             // first = launch 3 (profiled)
      if (layer==0 && step==0) k_nobs<<<ngrid, nblk>>>();
      k_gred<<<(TRI*NN)/256, 256>>>();
      k_ginv<<<NN/64, 64>>>();
      k_psiA<<<igrid, iblk>>>(X, step, 0);
      k_rhsB<<<igrid, iblk>>>(X, step, 0);
      k_beta1<<<NN/128, 128>>>(step);
      k_psiA<<<igrid, iblk>>>(X, step, 1);
      k_rhsB<<<igrid, iblk>>>(X, step, 1);
      k_beta2<<<NN/128, 128>>>(step);
    }
  }
  k_out<<<(MM*NN/4)/256, 256>>>(out);
}